// round 10
// baseline (speedup 1.0000x reference)
#include <cuda_runtime.h>
#include <cuda_fp16.h>

#define NB    4
#define NSEQ  4096
#define DIM   32
#define CDIM  256
#define NTOK  (NB * NSEQ)   // 16384

// -------- device-global scratch (no allocation allowed) -------------------
__device__ __align__(16) unsigned g_xh32[NTOK * 128];
__device__ __align__(16) unsigned g_xl32[NTOK * 128];
__device__ __align__(16) unsigned g_qhh32[NTOK * 16];
__device__ __align__(16) unsigned g_qhl32[NTOK * 16];
__device__ __align__(16) unsigned g_khh32[NTOK * 16];
__device__ __align__(16) unsigned g_khl32[NTOK * 16];
__device__ __align__(16) unsigned g_vh32[NTOK * 128];
__device__ __align__(16) unsigned g_ah32[NTOK * 128];
__device__ __align__(16) unsigned g_al32[NTOK * 128];
__device__ __align__(16) unsigned wqh32[128 * 32],  wql32[128 * 32];
__device__ __align__(16) unsigned wkh32[128 * 32],  wkl32[128 * 32];
__device__ __align__(16) unsigned wvh32[128 * 256], wvl32[128 * 256];
__device__ __align__(16) unsigned woh32[128 * 256], wol32[128 * 256];

// -------- fp16 helpers ----------------------------------------------------
__device__ __forceinline__ unsigned f2h2(float a, float b) {
    unsigned r;
    asm("cvt.rn.f16x2.f32 %0,%1,%2;" : "=r"(r) : "f"(b), "f"(a));
    return r;
}
__device__ __forceinline__ void splitf(float v, float& h, float& l) {
    __half hh = __float2half_rn(v);
    h = __half2float(hh);
    l = v - h;
}
__device__ __forceinline__ void mma_f16(float* cd, const unsigned* a,
                                        unsigned b0, unsigned b1) {
    asm volatile(
        "mma.sync.aligned.m16n8k16.row.col.f32.f16.f16.f32 "
        "{%0,%1,%2,%3},{%4,%5,%6,%7},{%8,%9},{%0,%1,%2,%3};"
        : "+f"(cd[0]), "+f"(cd[1]), "+f"(cd[2]), "+f"(cd[3])
        : "r"(a[0]), "r"(a[1]), "r"(a[2]), "r"(a[3]), "r"(b0), "r"(b1));
}

// ---------------------------------------------------------------------------
// Prep: convert x and weights to hi/lo half2 once.
// ---------------------------------------------------------------------------
__global__ __launch_bounds__(256) void prep_x(const float* __restrict__ x)
{
    int i = blockIdx.x * 256 + threadIdx.x;
    if (i >= NTOK * 128) return;
    float2 v = *(const float2*)(x + 2 * i);
    float h0, l0, h1, l1;
    splitf(v.x, h0, l0); splitf(v.y, h1, l1);
    g_xh32[i] = f2h2(h0, h1);
    g_xl32[i] = f2h2(l0, l1);
}

__global__ __launch_bounds__(256) void prep_w(
    const float* __restrict__ wq, const float* __restrict__ wk,
    const float* __restrict__ wv, const float* __restrict__ wo)
{
    int i = blockIdx.x * 256 + threadIdx.x;
    float w0, w1; unsigned *dh, *dl; int idx;
    if (i < 4096) {
        int col = i & 31, kk = i >> 5;
        w0 = wq[(2 * kk) * 32 + col]; w1 = wq[(2 * kk + 1) * 32 + col];
        dh = wqh32; dl = wql32; idx = i;
    } else if (i < 8192) {
        int j = i - 4096, col = j & 31, kk = j >> 5;
        w0 = wk[(2 * kk) * 32 + col]; w1 = wk[(2 * kk + 1) * 32 + col];
        dh = wkh32; dl = wkl32; idx = j;
    } else if (i < 40960) {
        int j = i - 8192, col = j & 255, kk = j >> 8;
        w0 = wv[(2 * kk) * 256 + col]; w1 = wv[(2 * kk + 1) * 256 + col];
        dh = wvh32; dl = wvl32; idx = j;
    } else if (i < 73728) {
        int j = i - 40960, col = j & 255, kk = j >> 8;
        w0 = wo[(2 * kk) * 256 + col]; w1 = wo[(2 * kk + 1) * 256 + col];
        dh = woh32; dl = wol32; idx = j;
    } else return;
    float h0, l0, h1, l1;
    splitf(w0, h0, l0); splitf(w1, h1, l1);
    dh[idx] = f2h2(h0, h1);
    dl[idx] = f2h2(l0, l1);
}

// ---------------------------------------------------------------------------
// Kernel 1: QKV projection, fp16 MMA 2-term hi/lo split. Pure-copy staging.
// CTA tile 128x64, 8 warps. Epilogue writes q/k as scaled hi/lo fp16 pairs,
// v as fp16 pairs.
// ---------------------------------------------------------------------------
#define XP 36
#define WP 72
#define GEMM_SMEM ((2 * 128 * XP + 2 * 32 * WP) * 4)

__global__ __launch_bounds__(256) void qkv_kernel(
    const float* __restrict__ bq, const float* __restrict__ bk,
    const float* __restrict__ bv)
{
    extern __shared__ unsigned sq[];
    unsigned* Xh = sq;
    unsigned* Xl = sq + 128 * XP;
    unsigned* Wh = sq + 2 * 128 * XP;
    unsigned* Wl = sq + 2 * 128 * XP + 32 * WP;

    const int n0  = blockIdx.x * 64;
    const int m0  = blockIdx.y * 128;
    const int tid = threadIdx.x;
    const int w = tid >> 5, lane = tid & 31, g = lane >> 2, c = lane & 3;

    float acc[8][4];
#pragma unroll
    for (int nt = 0; nt < 8; nt++)
#pragma unroll
        for (int i = 0; i < 4; i++) acc[nt][i] = 0.f;

    for (int k0 = 0; k0 < CDIM; k0 += 64) {
        const int kb = k0 >> 1;
        for (int i = tid; i < 128 * 32; i += 256) {
            int kk = i & 31, row = i >> 5;
            Xh[row * XP + kk] = g_xh32[(m0 + row) * 128 + kb + kk];
            Xl[row * XP + kk] = g_xl32[(m0 + row) * 128 + kb + kk];
        }
        for (int i = tid; i < 32 * 64; i += 256) {
            int col = i & 63, kk2 = i >> 6;
            int gkk = kb + kk2, gc = n0 + col;
            unsigned wh, wl;
            if (gc < 32)      { wh = wqh32[gkk * 32 + gc];       wl = wql32[gkk * 32 + gc]; }
            else if (gc < 64) { wh = wkh32[gkk * 32 + gc - 32];  wl = wkl32[gkk * 32 + gc - 32]; }
            else              { wh = wvh32[gkk * 256 + gc - 64]; wl = wvl32[gkk * 256 + gc - 64]; }
            Wh[kk2 * WP + col] = wh;
            Wl[kk2 * WP + col] = wl;
        }
        __syncthreads();

        const int rg = 16 * w + g;
#pragma unroll
        for (int ks = 0; ks < 4; ks++) {
            unsigned ah[4], al[4];
            ah[0] = Xh[rg * XP + 8 * ks + c];
            ah[1] = Xh[(rg + 8) * XP + 8 * ks + c];
            ah[2] = Xh[rg * XP + 8 * ks + c + 4];
            ah[3] = Xh[(rg + 8) * XP + 8 * ks + c + 4];
            al[0] = Xl[rg * XP + 8 * ks + c];
            al[1] = Xl[(rg + 8) * XP + 8 * ks + c];
            al[2] = Xl[rg * XP + 8 * ks + c + 4];
            al[3] = Xl[(rg + 8) * XP + 8 * ks + c + 4];
#pragma unroll
            for (int nt = 0; nt < 8; nt++) {
                unsigned bh0 = Wh[(8 * ks + c) * WP + 8 * nt + g];
                unsigned bh1 = Wh[(8 * ks + c + 4) * WP + 8 * nt + g];
                unsigned bl0 = Wl[(8 * ks + c) * WP + 8 * nt + g];
                unsigned bl1 = Wl[(8 * ks + c + 4) * WP + 8 * nt + g];
                mma_f16(acc[nt], ah, bh0, bh1);
                mma_f16(acc[nt], al, bh0, bh1);
                mma_f16(acc[nt], ah, bl0, bl1);
            }
        }
        __syncthreads();
    }

    const float scale = 0.17677669529663687f;   // 1/sqrt(32)
    const int r0 = m0 + 16 * w + g, r1 = r0 + 8;
#pragma unroll
    for (int nt = 0; nt < 8; nt++) {
        int gc = n0 + 8 * nt + 2 * c;
        float h0, l0, h1, l1;
        if (gc < 32) {
            float b0v = bq[gc], b1v = bq[gc + 1];
            float v0 = (acc[nt][0] + b0v) * scale, v1 = (acc[nt][1] + b1v) * scale;
            float v2 = (acc[nt][2] + b0v) * scale, v3 = (acc[nt][3] + b1v) * scale;
            splitf(v0, h0, l0); splitf(v1, h1, l1);
            g_qhh32[r0 * 16 + (gc >> 1)] = f2h2(h0, h1);
            g_qhl32[r0 * 16 + (gc >> 1)] = f2h2(l0, l1);
            splitf(v2, h0, l0); splitf(v3, h1, l1);
            g_qhh32[r1 * 16 + (gc >> 1)] = f2h2(h0, h1);
            g_qhl32[r1 * 16 + (gc >> 1)] = f2h2(l0, l1);
        } else if (gc < 64) {
            int kc = gc - 32;
            float b0v = bk[kc], b1v = bk[kc + 1];
            float v0 = acc[nt][0] + b0v, v1 = acc[nt][1] + b1v;
            float v2 = acc[nt][2] + b0v, v3 = acc[nt][3] + b1v;
            splitf(v0, h0, l0); splitf(v1, h1, l1);
            g_khh32[r0 * 16 + (kc >> 1)] = f2h2(h0, h1);
            g_khl32[r0 * 16 + (kc >> 1)] = f2h2(l0, l1);
            splitf(v2, h0, l0); splitf(v3, h1, l1);
            g_khh32[r1 * 16 + (kc >> 1)] = f2h2(h0, h1);
            g_khl32[r1 * 16 + (kc >> 1)] = f2h2(l0, l1);
        } else {
            int vc = gc - 64;
            float b0v = bv[vc], b1v = bv[vc + 1];
            g_vh32[r0 * 128 + (vc >> 1)] = f2h2(acc[nt][0] + b0v, acc[nt][1] + b1v);
            g_vh32[r1 * 128 + (vc >> 1)] = f2h2(acc[nt][2] + b0v, acc[nt][3] + b1v);
        }
    }
}

// ---------------------------------------------------------------------------
// Kernel 2: flash attention, fp16 MMA, repartitioned PV.
// Grid (32, 4), 256 threads = 8 warps, 1 CTA/SM.
// S phase: warp w -> rows 16w..16w+15 x 64 keys (hi/lo split QK^T).
// PV phase: warp (wm=w>>2, wn=w&3) -> rows 64wm..+63 x cols 64wn..+63.
// Alphas / inv-l broadcast via SMEM.
// ---------------------------------------------------------------------------
#define KTP 72
#define VSP 264
#define PSP 36
#define SA_OFF (2 * 16 * KTP + 32 * VSP + 128 * PSP)
#define ATTN_SMEM ((SA_OFF + 256) * 4)

__global__ __launch_bounds__(256, 1) void attn_kernel()
{
    extern __shared__ unsigned sa[];
    unsigned* Kth = sa;                       // 16 x 72
    unsigned* Ktl = sa + 16 * KTP;            // 16 x 72
    unsigned* Vs  = sa + 2 * 16 * KTP;        // 32 x 264 (key-pair half2)
    unsigned* Ps  = sa + 2 * 16 * KTP + 32 * VSP;   // 128 x 36 (key-pair half2)
    float* sAlpha = (float*)(sa + SA_OFF);    // 128
    float* sInvL  = sAlpha + 128;             // 128

    const int b   = blockIdx.y;
    const int q0  = blockIdx.x * 128;
    const int tid = threadIdx.x;
    const int w = tid >> 5, lane = tid & 31, g = lane >> 2, c = lane & 3;
    const int wm = w >> 2, wn = w & 3;

    // ---- preload Q fragments (pre-scaled hi/lo fp16 from qkv) ----
    unsigned qah[2][4], qal[2][4];
    {
        const unsigned* qh = g_qhh32 + (b * NSEQ + q0 + 16 * w + g) * 16;
        const unsigned* ql = g_qhl32 + (b * NSEQ + q0 + 16 * w + g) * 16;
#pragma unroll
        for (int ks = 0; ks < 2; ks++) {
            qah[ks][0] = qh[8 * ks + c];        qal[ks][0] = ql[8 * ks + c];
            qah[ks][1] = qh[128 + 8 * ks + c];  qal[ks][1] = ql[128 + 8 * ks + c];
            qah[ks][2] = qh[8 * ks + c + 4];    qal[ks][2] = ql[8 * ks + c + 4];
            qah[ks][3] = qh[128 + 8 * ks + c + 4]; qal[ks][3] = ql[128 + 8 * ks + c + 4];
        }
    }

    float o[4][8][4];
#pragma unroll
    for (int mt = 0; mt < 4; mt++)
#pragma unroll
        for (int nt = 0; nt < 8; nt++)
#pragma unroll
            for (int i = 0; i < 4; i++) o[mt][nt][i] = 0.f;
    float m0r = -3.0e38f, m1r = -3.0e38f, l0r = 0.f, l1r = 0.f;

    for (int j0 = 0; j0 < NSEQ; j0 += 64) {
        // ---- stage K hi/lo (copy, transpose scatter) ----
        const unsigned* kh = g_khh32 + (b * NSEQ + j0) * 16;
        const unsigned* kl = g_khl32 + (b * NSEQ + j0) * 16;
        for (int i = tid; i < 64 * 16; i += 256) {
            int dd = i & 15, key = i >> 4;
            Kth[dd * KTP + key] = kh[key * 16 + dd];
            Ktl[dd * KTP + key] = kl[key * 16 + dd];
        }
        // ---- stage V: fp16, interleave key pairs via PRMT ----
        const unsigned* vg = g_vh32 + (b * NSEQ + j0) * 128;
        for (int i = tid; i < 32 * 128; i += 256) {
            int cp = i & 127, kk = i >> 7;     // cp = column pair
            unsigned a  = vg[(2 * kk) * 128 + cp];
            unsigned bb = vg[(2 * kk + 1) * 128 + cp];
            unsigned e = __byte_perm(a, bb, 0x5410);   // even col, keys (2kk,2kk+1)
            unsigned d = __byte_perm(a, bb, 0x7632);   // odd col
            *(uint2*)&Vs[kk * VSP + 2 * cp] = make_uint2(e, d);
        }
        __syncthreads();

        // ---- S = Q K^T (3-term hi/lo fp16) ----
        float sacc[8][4];
#pragma unroll
        for (int nt = 0; nt < 8; nt++)
#pragma unroll
            for (int i = 0; i < 4; i++) sacc[nt][i] = 0.f;
#pragma unroll
        for (int ks = 0; ks < 2; ks++) {
            const unsigned* kh0 = &Kth[(8 * ks + c) * KTP + g];
            const unsigned* kh1 = &Kth[(8 * ks + c + 4) * KTP + g];
            const unsigned* kl0 = &Ktl[(8 * ks + c) * KTP + g];
            const unsigned* kl1 = &Ktl[(8 * ks + c + 4) * KTP + g];
#pragma unroll
            for (int nt = 0; nt < 8; nt++) {
                unsigned bh0 = kh0[8 * nt], bh1 = kh1[8 * nt];
                unsigned bl0 = kl0[8 * nt], bl1 = kl1[8 * nt];
                mma_f16(sacc[nt], qah[ks], bh0, bh1);
                mma_f16(sacc[nt], qal[ks], bh0, bh1);
                mma_f16(sacc[nt], qah[ks], bl0, bl1);
            }
        }

        // ---- online softmax (rows 16w+g, 16w+g+8) ----
        float mt0 = -3.0e38f, mt1 = -3.0e38f;
#pragma unroll
        for (int nt = 0; nt < 8; nt++) {
            mt0 = fmaxf(mt0, fmaxf(sacc[nt][0], sacc[nt][1]));
            mt1 = fmaxf(mt1, fmaxf(sacc[nt][2], sacc[nt][3]));
        }
        mt0 = fmaxf(mt0, __shfl_xor_sync(0xffffffffu, mt0, 1));
        mt0 = fmaxf(mt0, __shfl_xor_sync(0xffffffffu, mt0, 2));
        mt1 = fmaxf(mt1, __shfl_xor_sync(0xffffffffu, mt1, 1));
        mt1 = fmaxf(mt1, __shfl_xor_sync(0xffffffffu, mt1, 2));
        float mnew0 = fmaxf(m0r, mt0), mnew1 = fmaxf(m1r, mt1);
        float alpha0 = __expf(m0r - mnew0), alpha1 = __expf(m1r - mnew1);

        float ps0 = 0.f, ps1 = 0.f;
#pragma unroll
        for (int nt = 0; nt < 8; nt++) {
            float p0 = __expf(sacc[nt][0] - mnew0);
            float p1 = __expf(sacc[nt][1] - mnew0);
            float p2 = __expf(sacc[nt][2] - mnew1);
            float p3 = __expf(sacc[nt][3] - mnew1);
            ps0 += p0 + p1; ps1 += p2 + p3;
            Ps[(16 * w + g) * PSP + 4 * nt + c]     = f2h2(p0, p1);
            Ps[(16 * w + g + 8) * PSP + 4 * nt + c] = f2h2(p2, p3);
        }
        ps0 += __shfl_xor_sync(0xffffffffu, ps0, 1);
        ps0 += __shfl_xor_sync(0xffffffffu, ps0, 2);
        ps1 += __shfl_xor_sync(0xffffffffu, ps1, 1);
        ps1 += __shfl_xor_sync(0xffffffffu, ps1, 2);
        l0r = l0r * alpha0 + ps0;
        l1r = l1r * alpha1 + ps1;
        m0r = mnew0; m1r = mnew1;
        if (c == 0) {
            sAlpha[16 * w + g]     = alpha0;
            sAlpha[16 * w + g + 8] = alpha1;
        }
        __syncthreads();   // P + alpha visible to all warps

        // ---- rescale + PV (warp tile: 64 rows x 64 cols) ----
        float a0[4], a1[4];
        bool need = false;
#pragma unroll
        for (int mt = 0; mt < 4; mt++) {
            a0[mt] = sAlpha[64 * wm + 16 * mt + g];
            a1[mt] = sAlpha[64 * wm + 16 * mt + g + 8];
            need |= (a0[mt] != 1.f) | (a1[mt] != 1.f);
        }
        if (__any_sync(0xffffffffu, need)) {
#pragma unroll
            for (int mt = 0; mt < 4; mt++)
#pragma unroll
                for (int nt = 0; nt < 8; nt++) {
                    o[mt][nt][0] *= a0[mt]; o[mt][nt][1] *= a0[mt];
                    o[mt][nt][2] *= a1[mt]; o[mt][nt][3] *= a1[mt];
                }
        }
#pragma unroll
        for (int ks = 0; ks < 4; ks++) {
            unsigned pa[4][4];
#pragma unroll
            for (int mt = 0; mt < 4; mt++) {
                int r = 64 * wm + 16 * mt + g;
                pa[mt][0] = Ps[r * PSP + 8 * ks + c];
                pa[mt][1] = Ps[(r + 8) * PSP + 8 * ks + c];
                pa[mt][2] = Ps[r * PSP + 8 * ks + c + 4];
                pa[mt][3] = Ps[(r + 8) * PSP + 8 * ks + c + 4];
            }
            const unsigned* vr0 = &Vs[(8 * ks + c) * VSP + 64 * wn + g];
            const unsigned* vr1 = &Vs[(8 * ks + c + 4) * VSP + 64 * wn + g];
#pragma unroll
            for (int nt = 0; nt < 8; nt++) {
                unsigned b0 = vr0[8 * nt], b1 = vr1[8 * nt];
#pragma unroll
                for (int mt = 0; mt < 4; mt++)
                    mma_f16(o[mt][nt], pa[mt], b0, b1);
            }
        }
        __syncthreads();   // PV done before next staging / P overwrite
    }

    // ---- normalize + store attended as hi/lo fp16 pairs ----
    if (c == 0) {
        sInvL[16 * w + g]     = 1.f / l0r;
        sInvL[16 * w + g + 8] = 1.f / l1r;
    }
    __syncthreads();
#pragma unroll
    for (int mt = 0; mt < 4; mt++) {
        int r = 64 * wm + 16 * mt + g;
        float i0 = sInvL[r], i1 = sInvL[r + 8];
        int gr0 = (b * NSEQ + q0 + r) * 128;
        int gr1 = gr0 + 8 * 128;
#pragma unroll
        for (int nt = 0; nt < 8; nt++) {
            int c2 = 32 * wn + 4 * nt + c;
            float h0, l0, h1, l1;
            float v0 = o[mt][nt][0] * i0, v1 = o[mt][nt][1] * i0;
            splitf(v0, h0, l0); splitf(v1, h1, l1);
            g_ah32[gr0 + c2] = f2h2(h0, h1);
            g_al32[gr0 + c2] = f2h2(l0, l1);
            float v2 = o[mt][nt][2] * i1, v3 = o[mt][nt][3] * i1;
            splitf(v2, h0, l0); splitf(v3, h1, l1);
            g_ah32[gr1 + c2] = f2h2(h0, h1);
            g_al32[gr1 + c2] = f2h2(l0, l1);
        }
    }
}

// ---------------------------------------------------------------------------
// Kernel 3: output projection + residual, fp16 MMA 2-term split, copy staging.
// ---------------------------------------------------------------------------
__global__ __launch_bounds__(256) void proj_kernel(
    const float* __restrict__ x, const float* __restrict__ bo,
    float* __restrict__ out)
{
    extern __shared__ unsigned sp[];
    unsigned* Xh = sp;
    unsigned* Xl = sp + 128 * XP;
    unsigned* Wh = sp + 2 * 128 * XP;
    unsigned* Wl = sp + 2 * 128 * XP + 32 * WP;

    const int n0  = blockIdx.x * 64;
    const int m0  = blockIdx.y * 128;
    const int tid = threadIdx.x;
    const int w = tid >> 5, lane = tid & 31, g = lane >> 2, c = lane & 3;

    float acc[8][4];
#pragma unroll
    for (int nt = 0; nt < 8; nt++)
#pragma unroll
        for (int i = 0; i < 4; i++) acc[nt][i] = 0.f;

    for (int k0 = 0; k0 < CDIM; k0 += 64) {
        const int kb = k0 >> 1;
        for (int i = tid; i < 128 * 32; i += 256) {
            int kk = i & 31, row = i >> 5;
            Xh[row * XP + kk] = g_ah32[(m0 + row) * 128 + kb + kk];
            Xl[row * XP + kk] = g_al32[(m0 + row) * 128 + kb + kk];
        }
        for (int i = tid; i < 32 * 64; i += 256) {
            int col = i & 63, kk2 = i >> 6;
            Wh[kk2 * WP + col] = woh32[(kb + kk2) * 256 + n0 + col];
            Wl[kk2 * WP + col] = wol32[(kb + kk2) * 256 + n0 + col];
        }
        __syncthreads();

        const int rg = 16 * w + g;
#pragma unroll
        for (int ks = 0; ks < 4; ks++) {
            unsigned ah[4], al[4];
            ah[0] = Xh[rg * XP + 8 * ks + c];
            ah[1] = Xh[(rg + 8) * XP + 8 * ks + c];
            ah[2] = Xh[rg * XP + 8 * ks + c + 4];
            ah[3] = Xh[(rg + 8) * XP + 8 * ks + c + 4];
            al[0] = Xl[rg * XP + 8 * ks + c];
            al[1] = Xl[(rg + 8) * XP + 8 * ks + c];
            al[2] = Xl[rg * XP + 8 * ks + c + 4];
            al[3] = Xl[(rg + 8) * XP + 8 * ks + c + 4];
#pragma unroll
            for (int nt = 0; nt < 8; nt++) {
                unsigned bh0 = Wh[(8 * ks + c) * WP + 8 * nt + g];
                unsigned bh1 = Wh[(8 * ks + c + 4) * WP + 8 * nt + g];
                unsigned bl0 = Wl[(8 * ks + c) * WP + 8 * nt + g];
                unsigned bl1 = Wl[(8 * ks + c + 4) * WP + 8 * nt + g];
                mma_f16(acc[nt], ah, bh0, bh1);
                mma_f16(acc[nt], al, bh0, bh1);
                mma_f16(acc[nt], ah, bl0, bl1);
            }
        }
        __syncthreads();
    }

    const int r0 = m0 + 16 * w + g, r1 = r0 + 8;
#pragma unroll
    for (int nt = 0; nt < 8; nt++) {
        int gc = n0 + 8 * nt + 2 * c;
        float b0 = bo[gc], b1 = bo[gc + 1];
        float2 x0 = *(const float2*)&x[r0 * CDIM + gc];
        float2 x1 = *(const float2*)&x[r1 * CDIM + gc];
        *(float2*)&out[r0 * CDIM + gc] =
            make_float2(x0.x + acc[nt][0] + b0, x0.y + acc[nt][1] + b1);
        *(float2*)&out[r1 * CDIM + gc] =
            make_float2(x1.x + acc[nt][2] + b0, x1.y + acc[nt][3] + b1);
    }
}

// ---------------------------------------------------------------------------
extern "C" void kernel_launch(void* const* d_in, const int* in_sizes, int n_in,
                              void* d_out, int out_size)
{
    const float* x  = (const float*)d_in[0];
    const float* wq = (const float*)d_in[1];
    const float* bq = (const float*)d_in[2];
    const float* wk = (const float*)d_in[3];
    const float* bk = (const float*)d_in[4];
    const float* wv = (const float*)d_in[5];
    const float* bv = (const float*)d_in[6];
    const float* wo = (const float*)d_in[7];
    const float* bo = (const float*)d_in[8];
    float* out = (float*)d_out;

    cudaFuncSetAttribute(qkv_kernel,
                         cudaFuncAttributeMaxDynamicSharedMemorySize, GEMM_SMEM);
    cudaFuncSetAttribute(proj_kernel,
                         cudaFuncAttributeMaxDynamicSharedMemorySize, GEMM_SMEM);
    cudaFuncSetAttribute(attn_kernel,
                         cudaFuncAttributeMaxDynamicSharedMemorySize, ATTN_SMEM);

    prep_x<<<(NTOK * 128) / 256, 256>>>(x);
    prep_w<<<288, 256>>>(wq, wk, wv, wo);
    qkv_kernel<<<dim3(5, 128), 256, GEMM_SMEM>>>(bq, bk, bv);
    attn_kernel<<<dim3(NSEQ / 128, NB), 256, ATTN_SMEM>>>();
    proj_kernel<<<dim3(4, 128), 256, GEMM_SMEM>>>(x, bo, out);
}